// round 15
// baseline (speedup 1.0000x reference)
#include <cuda_runtime.h>
#include <cuda_bf16.h>
#include <math.h>
#include <stdint.h>

#define EPS 1e-6f
#define MAXB 1024
#define MAXN 40000
#define MAXD 512

// ===================== fast math =====================
__device__ __forceinline__ float fast_lg2(float x) {
    float r; asm("lg2.approx.f32 %0, %1;" : "=f"(r) : "f"(x)); return r;
}
__device__ __forceinline__ float fast_ex2(float x) {
    float r; asm("ex2.approx.f32 %0, %1;" : "=f"(r) : "f"(x)); return r;
}
__device__ __forceinline__ float fast_sqrt(float x) {
    float r; asm("sqrt.approx.f32 %0, %1;" : "=f"(r) : "f"(x)); return r;
}
__device__ __forceinline__ uint32_t smem_u32(const void* p) {
    uint32_t a;
    asm("{ .reg .u64 t; cvta.to.shared.u64 t, %1; cvt.u32.u64 %0, t; }" : "=r"(a) : "l"(p));
    return a;
}

// ===================== mma.sync helpers =====================
#define LDSM_X4(r0, r1, r2, r3, addr)                                          \
    asm volatile("ldmatrix.sync.aligned.m8n8.x4.shared.b16 {%0,%1,%2,%3}, [%4];" \
        : "=r"(r0), "=r"(r1), "=r"(r2), "=r"(r3) : "r"(addr))

#define MMA16816(c, a, b0, b1)                                                 \
    asm volatile("mma.sync.aligned.m16n8k16.row.col.f32.bf16.bf16.f32 "        \
        "{%0,%1,%2,%3}, {%4,%5,%6,%7}, {%8,%9}, {%0,%1,%2,%3};"                \
        : "+f"((c)[0]), "+f"((c)[1]), "+f"((c)[2]), "+f"((c)[3])               \
        : "r"((a)[0]), "r"((a)[1]), "r"((a)[2]), "r"((a)[3]), "r"(b0), "r"(b1))

__device__ __forceinline__ void cp16(uint32_t dst, const void* src, bool pred) {
    int sz = pred ? 16 : 0;   // src-size 0 => zero-fill (keeps OOB tiles clean)
    asm volatile("cp.async.cg.shared.global [%0], [%1], 16, %2;"
        :: "r"(dst), "l"(src), "r"(sz) : "memory");
}
#define CP_COMMIT() asm volatile("cp.async.commit_group;" ::: "memory")
#define CP_WAIT(n)  asm volatile("cp.async.wait_group %0;" :: "n"(n) : "memory")

// ===================== scratch =====================
__device__ __align__(16) __nv_bfloat16 g_Qb[MAXB * MAXD];
__device__ __align__(16) __nv_bfloat16 g_Cb[MAXN * MAXD];
__device__ float g_ysq[MAXN];
__device__ float g_eb[MAXN];
__device__ float g_rowc[MAXB * 8];
__device__ float g_sumexp[MAXB];

// ===================== fused prep: init + candidates + queries =====================
__global__ void hy_prep(const float* __restrict__ Q, const float* __restrict__ C,
                        const float* __restrict__ bias, const float* __restrict__ curv,
                        float* out, int B, int N, int d) {
    const int gtid = blockIdx.x * blockDim.x + threadIdx.x;
    const int w = gtid >> 5;
    const int lane = gtid & 31;
    if (gtid < B) g_sumexp[gtid] = 0.f;
    if (gtid == 0) out[0] = 0.f;

    if (w < N) {
        const float* row = C + (long)w * d;
        __nv_bfloat16* brow = g_Cb + (long)w * d;
        float s = 0.f;
        for (int k = lane * 4; k < d; k += 128) {
            float4 v = *reinterpret_cast<const float4*>(row + k);
            s += v.x*v.x + v.y*v.y + v.z*v.z + v.w*v.w;
            __nv_bfloat162* bp = reinterpret_cast<__nv_bfloat162*>(brow + k);
            bp[0] = __floats2bfloat162_rn(v.x, v.y);
            bp[1] = __floats2bfloat162_rn(v.z, v.w);
        }
        #pragma unroll
        for (int o = 16; o > 0; o >>= 1) s += __shfl_xor_sync(0xffffffffu, s, o);
        if (lane == 0) { g_ysq[w] = s; g_eb[w] = expf(bias[w]); }
    } else if (w < N + B) {
        const int q = w - N;
        const float* row = Q + (long)q * d;
        __nv_bfloat16* brow = g_Qb + (long)q * d;
        float s = 0.f;
        for (int k = lane * 4; k < d; k += 128) {
            float4 v = *reinterpret_cast<const float4*>(row + k);
            s += v.x*v.x + v.y*v.y + v.z*v.z + v.w*v.w;
            __nv_bfloat162* bp = reinterpret_cast<__nv_bfloat162*>(brow + k);
            bp[0] = __floats2bfloat162_rn(v.x, v.y);
            bp[1] = __floats2bfloat162_rn(v.z, v.w);
        }
        #pragma unroll
        for (int o = 16; o > 0; o >>= 1) s += __shfl_xor_sync(0xffffffffu, s, o);
        if (lane == 0) {
            float c  = curv[q];
            float xs = s;
            float sc = sqrtf(c + EPS);
            float Bq = 1.f - c * xs;
            float* rc = g_rowc + q * 8;
            rc[0] = c;  rc[1] = xs;  rc[2] = Bq;  rc[3] = Bq * Bq;
            rc[4] = c * c * xs;  rc[5] = sc;
            rc[6] = -1.f / (sc + EPS);
            rc[7] = 1.f / (sc + EPS) - EPS;
        }
    }
}

// ===================== main HMMA fused kernel (persistent, never-draining pipeline) =====================
#define BM 64
#define BN 128
#define BK 32
#define RSB 80                      // padded row stride bytes (64B data + 16 pad)
#define ATILE (BM * RSB)            // 5120
#define BTILE (BN * RSB)            // 10240
#define STAGE_B (ATILE + BTILE)     // 15360
#define STAGES 4
#define RC_OFF  (STAGES * STAGE_B)            // 61440
#define YSQ_OFF (RC_OFF + BM * 8 * 4)         // 63488
#define EB_OFF  (YSQ_OFF + BN * 4)            // 64000
#define SMEM_TOT (EB_OFF + BN * 4)            // 64512

#define STAGE_CONSTS(MM0, NN0) do {                                            \
    for (int idx = tid; idx < BM * 8; idx += 256) {                            \
        int r = idx >> 3, cc = idx & 7, gm = (MM0) + r;                        \
        rc_s[idx] = (gm < B) ? g_rowc[gm * 8 + cc] : 0.f;                      \
    }                                                                          \
    for (int idx = tid; idx < BN; idx += 256) {                                \
        int gn = (NN0) + idx;                                                  \
        ysq_s[idx] = (gn < N) ? g_ysq[gn] : 0.f;                               \
        eb_s[idx]  = (gn < N) ? g_eb[gn]  : 0.f;                               \
    }                                                                          \
} while (0)

#define SET_PTRS(MM0, NN0) do {                                                \
    int _gmA0 = (MM0) + lrow;                                                  \
    int _gnB0 = (NN0) + lrow, _gnB1 = (NN0) + lrow + 64;                       \
    okA0 = _gmA0 < B;  okB0 = _gnB0 < N;  okB1 = _gnB1 < N;                    \
    pA0 = g_Qb + (long)(okA0 ? _gmA0 : 0) * d + lc16 * 8;                      \
    pB0 = g_Cb + (long)(okB0 ? _gnB0 : 0) * d + lc16 * 8;                      \
    pB1 = g_Cb + (long)(okB1 ? _gnB1 : 0) * d + lc16 * 8;                      \
} while (0)

#define PF(SO) do {                                                            \
    cp16(dA0 + (SO), pA0, okA0);                                               \
    cp16(dB0 + (SO), pB0, okB0);  cp16(dB1 + (SO), pB1, okB1);                 \
    pA0 += BK; pB0 += BK; pB1 += BK;                                           \
} while (0)

__global__ __launch_bounds__(256, 3)
void hy_mma(int B, int N, int d, int nblk_m, int nblk_n) {
    extern __shared__ __align__(16) char smem[];
    const uint32_t sb = smem_u32(smem);

    const int tid = threadIdx.x;
    const int wid = tid >> 5;
    const int lane = tid & 31;
    const int NKT = d / BK;            // 16 (multiple of 4 required)
    const int total = nblk_m * nblk_n;

    int blk = blockIdx.x;
    if (blk >= total) return;
    int n0 = (blk / nblk_m) * BN;
    int m0 = (blk % nblk_m) * BM;

    float* rc_s  = reinterpret_cast<float*>(smem + RC_OFF);
    float* ysq_s = reinterpret_cast<float*>(smem + YSQ_OFF);
    float* eb_s  = reinterpret_cast<float*>(smem + EB_OFF);

    // loader geometry
    const int lrow = tid >> 2;          // 0..63
    const int lc16 = tid & 3;
    const uint32_t dA0 = sb + lrow * RSB + lc16 * 16;
    const uint32_t dB0 = sb + ATILE + lrow * RSB + lc16 * 16;
    const uint32_t dB1 = dB0 + 64 * RSB;

    bool okA0, okB0, okB1;
    const __nv_bfloat16 *pA0, *pB0, *pB1;

    // warp tile: 32(m) x 32(n); 8 warps: 2(m) x 4(n)
    const int wm = (wid & 1) * 32;
    const int wn = (wid >> 1) * 32;
    const uint32_t a_base = sb + (wm + (lane & 15)) * RSB + (lane >> 4) * 16;
    const uint32_t b_base = sb + ATILE + (wn + (lane >> 4) * 8 + (lane & 7)) * RSB
                               + ((lane >> 3) & 1) * 16;

    // first block: stage constants + fill pipeline (chunks 0..2)
    STAGE_CONSTS(m0, n0);
    SET_PTRS(m0, n0);
    #pragma unroll
    for (int s = 0; s < STAGES - 1; s++) {
        PF(s * STAGE_B);
        CP_COMMIT();
    }
    __syncthreads();

    float acc[2][4][4];
    #pragma unroll
    for (int mi = 0; mi < 2; mi++)
        #pragma unroll
        for (int ni = 0; ni < 4; ni++)
            #pragma unroll
            for (int q = 0; q < 4; q++) acc[mi][ni][q] = 0.f;

    for (;;) {
        const int nextblk = blk + gridDim.x;
        const bool hasNext = nextblk < total;

        // ---- k mainloop: const-folded 4-stage, prefetch distance 3 ----
        for (int kt = 0; kt < NKT; kt += 4) {
            #pragma unroll
            for (int su = 0; su < 4; su++) {
                CP_WAIT(2);
                __syncthreads();

                // prefetch global chunk (kt+su+3): current block tail flows into next block head
                if (kt + su + 3 < NKT || hasNext) {
                    PF(((su + 3) & 3) * STAGE_B);
                }
                CP_COMMIT();

                // after the LAST current-block prefetch, repoint loader at next block's chunk 0
                if (su == 0) {
                    if (kt == NKT - 4 && hasNext) {
                        int nn0 = (nextblk / nblk_m) * BN;
                        int nm0 = (nextblk % nblk_m) * BM;
                        SET_PTRS(nm0, nn0);
                    }
                }

                const uint32_t so = su * STAGE_B;   // compile-time stage offset
                #pragma unroll
                for (int ks = 0; ks < 2; ks++) {
                    uint32_t a[2][4];
                    #pragma unroll
                    for (int mi = 0; mi < 2; mi++)
                        LDSM_X4(a[mi][0], a[mi][1], a[mi][2], a[mi][3],
                                a_base + so + mi * 16 * RSB + ks * 32);
                    uint32_t b[2][4];
                    #pragma unroll
                    for (int g = 0; g < 2; g++)
                        LDSM_X4(b[g][0], b[g][1], b[g][2], b[g][3],
                                b_base + so + g * 16 * RSB + ks * 32);
                    #pragma unroll
                    for (int mi = 0; mi < 2; mi++)
                        #pragma unroll
                        for (int ni = 0; ni < 4; ni++)
                            MMA16816(acc[mi][ni], a[mi], b[ni >> 1][(ni & 1) * 2],
                                     b[ni >> 1][(ni & 1) * 2 + 1]);
                }
            }
        }

        // ---- epilogue for current block (3 MUFU per element) ----
        #pragma unroll
        for (int mi = 0; mi < 2; mi++) {
            #pragma unroll
            for (int half = 0; half < 2; half++) {
                const int mrow = wm + mi * 16 + half * 8 + (lane >> 2);
                const int gm = m0 + mrow;
                const float* rc = rc_s + mrow * 8;
                const float c    = rc[0];
                const float xs   = rc[1];
                const float Bq   = rc[2];
                const float Bq2  = rc[3];
                const float c2xs = rc[4];
                const float sc   = rc[5];
                const float p    = rc[6];
                const float mxsc = rc[7] * rc[5];   // maxn*sc  (z upper bound, < 1)
                const float m2c  = -2.f * c;
                const float m2Bq = -2.f * Bq;
                const float epsc = EPS * sc;        // lower clamp on s/denp

                float rowsum = 0.f;
                #pragma unroll
                for (int ni = 0; ni < 4; ni++) {
                    const int colp = wn + ni * 8 + 2 * (lane & 3);
                    const float2 vv = *reinterpret_cast<const float2*>(ysq_s + colp);
                    const float2 ee = *reinterpret_cast<const float2*>(eb_s + colp);
                    #pragma unroll
                    for (int q = 0; q < 2; q++) {
                        float u  = acc[mi][ni][half * 2 + q];
                        float v  = q ? vv.y : vv.x;
                        float eb = q ? ee.y : ee.x;
                        float t    = fmaf(-2.f, u, v);
                        float A    = fmaf(c, t, 1.f);
                        float denp = fmaf(c2xs, v, fmaf(m2c, u, 1.f)) + EPS;
                        float ns   = fmaf(Bq2, v, A * fmaf(m2Bq, u, A * xs));
                        float s    = sc * fast_sqrt(fmaxf(ns, 0.f));
                        // clamp z = s/denp into [EPS*sc, maxn*sc]
                        s = fminf(fmaxf(s, epsc * denp), mxsc * denp);
                        // e = ((denp-s)/(denp+s))^(1/(sc+EPS)) = ex2(p*(lg2(denp+s)-lg2(denp-s)))
                        float l = fast_lg2(denp + s) - fast_lg2(denp - s);
                        rowsum = fmaf(eb, fast_ex2(p * l), rowsum);
                    }
                }
                rowsum += __shfl_xor_sync(0xffffffffu, rowsum, 1);
                rowsum += __shfl_xor_sync(0xffffffffu, rowsum, 2);
                if ((lane & 3) == 0 && gm < B) atomicAdd(&g_sumexp[gm], rowsum);
            }
        }

        if (!hasNext) break;

        // advance to next block: restage constants (chunk prefetches already in flight)
        blk = nextblk;
        n0 = (blk / nblk_m) * BN;
        m0 = (blk % nblk_m) * BM;
        __syncthreads();                 // all warps done reading current consts
        STAGE_CONSTS(m0, n0);
        // (k-loop's first CP_WAIT+__syncthreads makes these stores visible)

        #pragma unroll
        for (int mi = 0; mi < 2; mi++)
            #pragma unroll
            for (int ni = 0; ni < 4; ni++)
                #pragma unroll
                for (int q = 0; q < 4; q++) acc[mi][ni][q] = 0.f;
    }
}

// ===================== finalize =====================
__global__ void hy_finalize(const float* __restrict__ Q, const float* __restrict__ C,
                            const float* __restrict__ bias, const int* __restrict__ tgt,
                            float* out, int B, int N, int d) {
    int w = (blockIdx.x * blockDim.x + threadIdx.x) >> 5;
    int lane = threadIdx.x & 31;
    if (w >= B) return;
    int t = tgt[w];
    const float* q  = Q + (long)w * d;
    const float* cd = C + (long)t * d;
    float s = 0.f;
    for (int k = lane * 4; k < d; k += 128) {
        float4 a = *reinterpret_cast<const float4*>(q + k);
        float4 b = *reinterpret_cast<const float4*>(cd + k);
        s += a.x*b.x + a.y*b.y + a.z*b.z + a.w*b.w;
    }
    #pragma unroll
    for (int o = 16; o > 0; o >>= 1) s += __shfl_xor_sync(0xffffffffu, s, o);
    if (lane == 0) {
        const float* rc = g_rowc + w * 8;
        float c = rc[0], xs = rc[1], Bq = rc[2], Bq2 = rc[3], c2xs = rc[4];
        float sc = rc[5], maxn = rc[7];
        float u = s, v = g_ysq[t];
        float tt  = fmaf(-2.f, u, v);
        float A   = fmaf(c, tt, 1.f);
        float den = fmaf(c2xs, v, fmaf(-2.f * c, u, 1.f));
        float ns  = fmaf(Bq2, v, A * fmaf(-2.f * Bq, u, A * xs));
        float r   = sqrtf(fmaxf(ns, 0.f));
        float dn  = r / (den + EPS);
        dn = fminf(fmaxf(dn, EPS), maxn);
        float z = fminf(sc * dn, 1.f - EPS);
        float dist = (2.f / (sc + EPS)) * atanhf(z);
        float tlogit = bias[t] - dist;
        float lse = logf(g_sumexp[w]);
        atomicAdd(out, (lse - tlogit) * (1.f / (float)B));
    }
}

// ===================== launch =====================
extern "C" void kernel_launch(void* const* d_in, const int* in_sizes, int n_in,
                              void* d_out, int out_size) {
    const float* Q    = (const float*)d_in[0];
    const float* C    = (const float*)d_in[1];
    const float* bias = (const float*)d_in[2];
    const float* curv = (const float*)d_in[3];
    const int*   tgt  = (const int*)d_in[4];
    float* out = (float*)d_out;

    int B = in_sizes[3];
    int N = in_sizes[2];
    int d = in_sizes[0] / B;

    hy_prep<<<((N + B) * 32 + 255) / 256, 256>>>(Q, C, bias, curv, out, B, N, d);

    static int nsm = -1;
    if (nsm < 0) {
        cudaDeviceGetAttribute(&nsm, cudaDevAttrMultiProcessorCount, 0);
        cudaFuncSetAttribute(hy_mma, cudaFuncAttributeMaxDynamicSharedMemorySize, SMEM_TOT);
    }
    int nblk_m = (B + BM - 1) / BM;          // 16
    int nblk_n = (N + BN - 1) / BN;          // 313
    int total = nblk_m * nblk_n;
    int grid = nsm * 3 < total ? nsm * 3 : total;
    hy_mma<<<grid, 256, SMEM_TOT>>>(B, N, d, nblk_m, nblk_n);

    hy_finalize<<<(B * 32 + 255) / 256, 256>>>(Q, C, bias, tgt, out, B, N, d);
}